// round 3
// baseline (speedup 1.0000x reference)
#include <cuda_runtime.h>
#include <cstdint>

// ---------------------------------------------------------------------------
// Problem constants
// ---------------------------------------------------------------------------
#define BATCH 16
#define CDIM  768
#define SDIM  4096          // H*W = 64*64
#define KCOND 1024

// LN kernel tiling
#define PIX     16          // pixels per block
#define THREADS 256

// GEMM tiling
#define NCOLS   4           // output columns per block

// ---------------------------------------------------------------------------
// Scratch (no allocations allowed -> device globals)
// ---------------------------------------------------------------------------
__device__ __align__(16) float g_tmp0[BATCH * CDIM];
__device__ __align__(16) float g_tmp1[BATCH * CDIM];

// ---------------------------------------------------------------------------
// Small GEMM: out[b,n] = bias[n] + sum_k X[b,k] * W[n,k]
// Thread map: b = tid>>4 (16 batches), kg = tid&15 (16 k-groups).
// NCOLS output columns per block. float4 loads, 4-step shfl reduce.
// ---------------------------------------------------------------------------
__global__ void __launch_bounds__(256) gemm16_multi(
    const float* __restrict__ X, const float* __restrict__ W,
    const float* __restrict__ bias, float* __restrict__ out, int K, int N)
{
    const int tid = threadIdx.x;
    const int b   = tid >> 4;       // 0..15
    const int kg  = tid & 15;       // 0..15
    const int n0  = blockIdx.x * NCOLS;

    const int K4    = K >> 2;
    const int iters = K4 >> 4;      // K/64: 16 for K=1024, 12 for K=768

    const float4* X4 = (const float4*)X + (size_t)b * K4;
    const float4* W4 = (const float4*)W;

    float acc[NCOLS];
#pragma unroll
    for (int j = 0; j < NCOLS; j++) acc[j] = 0.f;

    for (int i = 0; i < iters; i++) {
        const int k4 = kg + (i << 4);
        float4 x = __ldg(X4 + k4);
#pragma unroll
        for (int j = 0; j < NCOLS; j++) {
            float4 w = __ldg(W4 + (size_t)(n0 + j) * K4 + k4);
            acc[j] += w.x * x.x + w.y * x.y + w.z * x.z + w.w * x.w;
        }
    }

    // reduce across the 16 kg lanes (lane bits 0..3)
#pragma unroll
    for (int j = 0; j < NCOLS; j++) {
        acc[j] += __shfl_xor_sync(0xffffffffu, acc[j], 8);
        acc[j] += __shfl_xor_sync(0xffffffffu, acc[j], 4);
        acc[j] += __shfl_xor_sync(0xffffffffu, acc[j], 2);
        acc[j] += __shfl_xor_sync(0xffffffffu, acc[j], 1);
    }

    if (kg == 0) {
#pragma unroll
        for (int j = 0; j < NCOLS; j++)
            out[b * N + n0 + j] = acc[j] + __ldg(bias + n0 + j);
    }
}

// ---------------------------------------------------------------------------
// Fused broadcast-add + LayerNorm(C).
//   in : spatial [B, C, S]  (S contiguous), proj[B, C] broadcast over S
//   out: y[B, C, S], LN over C per (b, s). Spatial read exactly once.
//
// PIX=16 pixels/block, 50.3 KB smem -> 4 blocks/SM. Stats accumulated in
// registers during the load pass (no extra SMEM stats pass).
// Thread map: p4 = tid&3 (float4 within pixel row), c0 = tid>>2 (0..63).
// ---------------------------------------------------------------------------
__global__ void __launch_bounds__(THREADS) fused_add_ln(
    const float* __restrict__ spatial,
    const float* __restrict__ proj,
    const float* __restrict__ gamma,
    const float* __restrict__ beta,
    float* __restrict__ out)
{
    extern __shared__ float smem[];
    float* tile   = smem;                     // CDIM * PIX          (49152 B)
    float* psum   = tile + CDIM * PIX;        // 8 warps * PIX       (512 B)
    float* psq    = psum + 8 * PIX;           // 8 warps * PIX       (512 B)
    float* mean_s = psq  + 8 * PIX;           // PIX
    float* rstd_s = mean_s + PIX;             // PIX

    const int tid = threadIdx.x;
    const int b   = blockIdx.x >> 8;          // SDIM/PIX = 256 blocks/batch
    const int s0  = (blockIdx.x & 255) * PIX;

    const int p4 = tid & 3;                   // float4 slot within 16-pixel row
    const int c0 = tid >> 2;                  // 0..63
    const int warp = tid >> 5;
    const int lane = tid & 31;

    const size_t gbase = (size_t)b * CDIM * SDIM + s0;
    const float* projb = proj + b * CDIM;

    float acc[4] = {0.f, 0.f, 0.f, 0.f};
    float asq[4] = {0.f, 0.f, 0.f, 0.f};

    // ---- load + broadcast add + register stats (one DRAM read) ----
#pragma unroll
    for (int it = 0; it < CDIM / 64; it++) {
        const int c = c0 + it * 64;
        float4 v = *(const float4*)(spatial + gbase + (size_t)c * SDIM + p4 * 4);
        float pj = __ldg(projb + c);
        v.x += pj; v.y += pj; v.z += pj; v.w += pj;
        acc[0] += v.x; asq[0] += v.x * v.x;
        acc[1] += v.y; asq[1] += v.y * v.y;
        acc[2] += v.z; asq[2] += v.z * v.z;
        acc[3] += v.w; asq[3] += v.w * v.w;
        *(float4*)(tile + c * PIX + p4 * 4) = v;
    }

    // ---- warp-level reduce over the c0 sub-groups (lane bits 2..4) ----
#pragma unroll
    for (int q = 0; q < 4; q++) {
        acc[q] += __shfl_xor_sync(0xffffffffu, acc[q], 4);
        acc[q] += __shfl_xor_sync(0xffffffffu, acc[q], 8);
        acc[q] += __shfl_xor_sync(0xffffffffu, acc[q], 16);
        asq[q] += __shfl_xor_sync(0xffffffffu, asq[q], 4);
        asq[q] += __shfl_xor_sync(0xffffffffu, asq[q], 8);
        asq[q] += __shfl_xor_sync(0xffffffffu, asq[q], 16);
    }
    if (lane < 4) {
#pragma unroll
        for (int q = 0; q < 4; q++) {
            psum[warp * PIX + lane * 4 + q] = acc[q];
            psq [warp * PIX + lane * 4 + q] = asq[q];
        }
    }
    __syncthreads();

    // ---- final per-pixel stats ----
    if (tid < PIX) {
        float s = 0.f, sq = 0.f;
#pragma unroll
        for (int w = 0; w < 8; w++) { s += psum[w * PIX + tid]; sq += psq[w * PIX + tid]; }
        const float inv = 1.0f / CDIM;
        float mu  = s * inv;
        float var = sq * inv - mu * mu;
        mean_s[tid] = mu;
        rstd_s[tid] = rsqrtf(var + 1e-5f);
    }
    __syncthreads();

    // ---- normalize + store ----
    const float4 mu4 = *(const float4*)(mean_s + p4 * 4);
    const float4 rs4 = *(const float4*)(rstd_s + p4 * 4);
#pragma unroll
    for (int it = 0; it < CDIM / 64; it++) {
        const int c = c0 + it * 64;
        float4 v = *(const float4*)(tile + c * PIX + p4 * 4);
        float g  = __ldg(gamma + c);
        float bt = __ldg(beta + c);
        v.x = (v.x - mu4.x) * rs4.x * g + bt;
        v.y = (v.y - mu4.y) * rs4.y * g + bt;
        v.z = (v.z - mu4.z) * rs4.z * g + bt;
        v.w = (v.w - mu4.w) * rs4.w * g + bt;
        *(float4*)(out + gbase + (size_t)c * SDIM + p4 * 4) = v;
    }
}

// ---------------------------------------------------------------------------
// Launcher
// ---------------------------------------------------------------------------
extern "C" void kernel_launch(void* const* d_in, const int* in_sizes, int n_in,
                              void* d_out, int out_size)
{
    const float* spatial     = (const float*)d_in[0];
    const float* conditioning= (const float*)d_in[1];
    const float* w_cond      = (const float*)d_in[2];
    const float* b_cond      = (const float*)d_in[3];
    const float* in_proj_w   = (const float*)d_in[4];
    const float* in_proj_b   = (const float*)d_in[5];
    const float* attn_out_w  = (const float*)d_in[6];
    const float* attn_out_b  = (const float*)d_in[7];
    const float* w_out       = (const float*)d_in[8];
    const float* b_out       = (const float*)d_in[9];
    const float* ln_gamma    = (const float*)d_in[10];
    const float* ln_beta     = (const float*)d_in[11];
    float* out = (float*)d_out;

    float *tmp0, *tmp1;
    cudaGetSymbolAddress((void**)&tmp0, g_tmp0);
    cudaGetSymbolAddress((void**)&tmp1, g_tmp1);

    const int smem_bytes = (CDIM * PIX + 16 * PIX + 2 * PIX) * sizeof(float);
    cudaFuncSetAttribute(fused_add_ln, cudaFuncAttributeMaxDynamicSharedMemorySize, smem_bytes);

    const int gg = CDIM / NCOLS;   // 192 blocks

    // cond = conditioning @ w_cond^T + b_cond
    gemm16_multi<<<gg, 256>>>(conditioning, w_cond, b_cond, tmp0, KCOND, CDIM);
    // v = cond @ wv^T + bv   (wv = in_proj_w rows [2C, 3C))
    gemm16_multi<<<gg, 256>>>(tmp0, in_proj_w + 2 * CDIM * CDIM, in_proj_b + 2 * CDIM,
                              tmp1, CDIM, CDIM);
    // attn = v @ attn_out_w^T + attn_out_b
    gemm16_multi<<<gg, 256>>>(tmp1, attn_out_w, attn_out_b, tmp0, CDIM, CDIM);
    // proj = attn @ w_out^T + b_out
    gemm16_multi<<<gg, 256>>>(tmp0, w_out, b_out, tmp1, CDIM, CDIM);

    // fused add + layernorm
    fused_add_ln<<<BATCH * (SDIM / PIX), THREADS, smem_bytes>>>(
        spatial, tmp1, ln_gamma, ln_beta, out);
}

// round 4
// speedup vs baseline: 1.1683x; 1.1683x over previous
#include <cuda_runtime.h>
#include <cstdint>

// ---------------------------------------------------------------------------
// Problem constants
// ---------------------------------------------------------------------------
#define BATCH 16
#define CDIM  768
#define SDIM  4096          // H*W = 64*64
#define KCOND 1024

#define PIX     32          // pixels per LN block
#define THREADS 256

// ---------------------------------------------------------------------------
// Scratch (no allocations allowed -> device globals)
// ---------------------------------------------------------------------------
__device__ __align__(16) float g_tmp0[BATCH * CDIM];
__device__ __align__(16) float g_tmp1[BATCH * CDIM];
__device__ unsigned g_barrier;

// ---------------------------------------------------------------------------
// Grid-wide software barrier. Requires ALL blocks co-resident (grid=96 on a
// 148-SM chip, 8 warps/block -> trivially resident). Counter is reset to 0
// by a memset node before each kernel launch.
// ---------------------------------------------------------------------------
__device__ __forceinline__ void grid_sync(unsigned target) {
    __syncthreads();
    if (threadIdx.x == 0) {
        __threadfence();                       // release our writes
        atomicAdd(&g_barrier, 1u);
        volatile unsigned* p = &g_barrier;
        while (*p < target) { }
        __threadfence();                       // acquire others' writes
    }
    __syncthreads();
}

// ---------------------------------------------------------------------------
// One GEMM phase: out[b,n] = bias[n] + sum_k X[b,k] * W[n,k], B=16.
// Warp-per-column: n = blk*8 + warp, lanes split K with float4 loads.
// XCG=true -> X read with .cg (L2 only): X was written by a previous phase.
// ---------------------------------------------------------------------------
template<bool XCG>
__device__ __forceinline__ void gemm_phase(
    const float* __restrict__ X, const float* __restrict__ W,
    const float* __restrict__ bias, float* __restrict__ out,
    int K4, int N)
{
    const int warp = threadIdx.x >> 5;
    const int lane = threadIdx.x & 31;
    const int n = blockIdx.x * 8 + warp;
    if (n >= N) return;

    const float4* W4 = (const float4*)W + (size_t)n * K4;
    const float4* X4 = (const float4*)X;

    float acc[BATCH];
#pragma unroll
    for (int b = 0; b < BATCH; b++) acc[b] = 0.f;

    for (int k4 = lane; k4 < K4; k4 += 32) {
        float4 w = __ldg(W4 + k4);
#pragma unroll
        for (int b = 0; b < BATCH; b++) {
            float4 x = XCG ? __ldcg(X4 + (size_t)b * K4 + k4)
                           : __ldg (X4 + (size_t)b * K4 + k4);
            acc[b] += w.x * x.x + w.y * x.y + w.z * x.z + w.w * x.w;
        }
    }
#pragma unroll
    for (int b = 0; b < BATCH; b++) {
#pragma unroll
        for (int off = 16; off; off >>= 1)
            acc[b] += __shfl_xor_sync(0xffffffffu, acc[b], off);
    }
    if (lane == 0) {
        float bs = __ldg(bias + n);
#pragma unroll
        for (int b = 0; b < BATCH; b++)
            out[b * N + n] = acc[b] + bs;
    }
}

// ---------------------------------------------------------------------------
// Entire GEMM chain in one launch, grid=96 x 256 threads.
//   tmp0 = cond @ Wc^T + bc        (K=1024)
//   tmp1 = tmp0 @ Wv^T + bv        (K=768)
//   tmp0 = tmp1 @ Wa^T + ba        (K=768)
//   tmp1 = tmp0 @ Wo^T + bo  = proj (K=768)
// ---------------------------------------------------------------------------
__global__ void __launch_bounds__(256) gemm_chain(
    const float* __restrict__ conditioning,
    const float* __restrict__ w_cond,  const float* __restrict__ b_cond,
    const float* __restrict__ wv,      const float* __restrict__ bv,
    const float* __restrict__ attn_w,  const float* __restrict__ attn_b,
    const float* __restrict__ w_out,   const float* __restrict__ b_out)
{
    gemm_phase<false>(conditioning, w_cond, b_cond, g_tmp0, KCOND / 4, CDIM);
    grid_sync(96);
    gemm_phase<true >(g_tmp0, wv,     bv,     g_tmp1, CDIM / 4, CDIM);
    grid_sync(192);
    gemm_phase<true >(g_tmp1, attn_w, attn_b, g_tmp0, CDIM / 4, CDIM);
    grid_sync(288);
    gemm_phase<true >(g_tmp0, w_out,  b_out,  g_tmp1, CDIM / 4, CDIM);
}

// ---------------------------------------------------------------------------
// Fused broadcast-add + LayerNorm(C), register-resident tile.
// PIX=32 pixels/block; thread holds 24 float4 (its slice of the tile) in
// registers. Stats via shfl + tiny smem cross-warp reduce. Spatial read once.
// Thread map: p4 = tid&7 (float4 slot of 32-pixel row), c0 = tid>>3 (0..31).
// ---------------------------------------------------------------------------
__global__ void __launch_bounds__(THREADS, 2) fused_add_ln(
    const float* __restrict__ spatial,
    const float* __restrict__ proj,
    const float* __restrict__ gamma,
    const float* __restrict__ beta,
    float* __restrict__ out)
{
    __shared__ float psum[8 * PIX];
    __shared__ float psq [8 * PIX];
    __shared__ float mean_s[PIX];
    __shared__ float rstd_s[PIX];

    const int tid = threadIdx.x;
    const int b   = blockIdx.x >> 7;          // SDIM/PIX = 128 blocks/batch
    const int s0  = (blockIdx.x & 127) * PIX;

    const int p4   = tid & 7;                 // float4 slot within 32-pixel row
    const int c0   = tid >> 3;                // 0..31
    const int warp = tid >> 5;
    const int lane = tid & 31;

    const size_t gbase = (size_t)b * CDIM * SDIM + s0 + p4 * 4;
    const float* projb = proj + b * CDIM;

    float4 v[24];                             // CDIM/32 = 24 rows per thread
    float acc[4] = {0.f, 0.f, 0.f, 0.f};
    float asq[4] = {0.f, 0.f, 0.f, 0.f};

    // ---- load + broadcast add + register stats (one DRAM read) ----
#pragma unroll
    for (int it = 0; it < 24; it++) {
        const int c = c0 + it * 32;
        float4 x = *(const float4*)(spatial + gbase + (size_t)c * SDIM);
        float pj = __ldg(projb + c);
        x.x += pj; x.y += pj; x.z += pj; x.w += pj;
        acc[0] += x.x; asq[0] += x.x * x.x;
        acc[1] += x.y; asq[1] += x.y * x.y;
        acc[2] += x.z; asq[2] += x.z * x.z;
        acc[3] += x.w; asq[3] += x.w * x.w;
        v[it] = x;
    }

    // ---- combine the 4 same-p4 lanes of this warp (lane bits 3,4) ----
#pragma unroll
    for (int q = 0; q < 4; q++) {
        acc[q] += __shfl_xor_sync(0xffffffffu, acc[q], 8);
        acc[q] += __shfl_xor_sync(0xffffffffu, acc[q], 16);
        asq[q] += __shfl_xor_sync(0xffffffffu, asq[q], 8);
        asq[q] += __shfl_xor_sync(0xffffffffu, asq[q], 16);
    }
    if (lane == p4) {                         // lanes 0..7
#pragma unroll
        for (int q = 0; q < 4; q++) {
            psum[warp * PIX + p4 * 4 + q] = acc[q];
            psq [warp * PIX + p4 * 4 + q] = asq[q];
        }
    }
    __syncthreads();

    // ---- final per-pixel stats ----
    if (tid < PIX) {
        float s = 0.f, sq = 0.f;
#pragma unroll
        for (int w = 0; w < 8; w++) { s += psum[w * PIX + tid]; sq += psq[w * PIX + tid]; }
        const float inv = 1.0f / CDIM;
        float mu  = s * inv;
        float var = sq * inv - mu * mu;
        mean_s[tid] = mu;
        rstd_s[tid] = rsqrtf(var + 1e-5f);
    }
    __syncthreads();

    // ---- normalize registers + store ----
    const float4 mu4 = *(const float4*)(mean_s + p4 * 4);
    const float4 rs4 = *(const float4*)(rstd_s + p4 * 4);
#pragma unroll
    for (int it = 0; it < 24; it++) {
        const int c = c0 + it * 32;
        float g  = __ldg(gamma + c);
        float bt = __ldg(beta + c);
        float4 x = v[it];
        x.x = (x.x - mu4.x) * rs4.x * g + bt;
        x.y = (x.y - mu4.y) * rs4.y * g + bt;
        x.z = (x.z - mu4.z) * rs4.z * g + bt;
        x.w = (x.w - mu4.w) * rs4.w * g + bt;
        *(float4*)(out + gbase + (size_t)c * SDIM) = x;
    }
}

// ---------------------------------------------------------------------------
// Launcher
// ---------------------------------------------------------------------------
extern "C" void kernel_launch(void* const* d_in, const int* in_sizes, int n_in,
                              void* d_out, int out_size)
{
    const float* spatial     = (const float*)d_in[0];
    const float* conditioning= (const float*)d_in[1];
    const float* w_cond      = (const float*)d_in[2];
    const float* b_cond      = (const float*)d_in[3];
    const float* in_proj_w   = (const float*)d_in[4];
    const float* in_proj_b   = (const float*)d_in[5];
    const float* attn_out_w  = (const float*)d_in[6];
    const float* attn_out_b  = (const float*)d_in[7];
    const float* w_out       = (const float*)d_in[8];
    const float* b_out       = (const float*)d_in[9];
    const float* ln_gamma    = (const float*)d_in[10];
    const float* ln_beta     = (const float*)d_in[11];
    float* out = (float*)d_out;

    float* tmp1;
    cudaGetSymbolAddress((void**)&tmp1, g_tmp1);
    unsigned* bar;
    cudaGetSymbolAddress((void**)&bar, g_barrier);

    // reset the grid barrier every call (graph-capturable memset node)
    cudaMemsetAsync(bar, 0, sizeof(unsigned), 0);

    // whole GEMM chain, one launch
    gemm_chain<<<96, 256>>>(conditioning,
                            w_cond, b_cond,
                            in_proj_w + 2 * CDIM * CDIM, in_proj_b + 2 * CDIM,
                            attn_out_w, attn_out_b,
                            w_out, b_out);

    // fused add + layernorm (proj lives in g_tmp1)
    fused_add_ln<<<BATCH * (SDIM / PIX), THREADS>>>(
        spatial, tmp1, ln_gamma, ln_beta, out);
}

// round 5
// speedup vs baseline: 1.4493x; 1.2406x over previous
#include <cuda_runtime.h>
#include <cstdint>

// ---------------------------------------------------------------------------
// Problem constants
// ---------------------------------------------------------------------------
#define BATCH 16
#define CDIM  768
#define SDIM  4096          // H*W = 64*64
#define KCOND 1024

#define PIX     32          // pixels per LN block
#define THREADS 256
#define REG_IT  12          // c-iterations kept in registers (of 24)

// ---------------------------------------------------------------------------
// Scratch (no allocations allowed -> device globals)
// ---------------------------------------------------------------------------
__device__ __align__(16) float g_tmp0[BATCH * CDIM];
__device__ __align__(16) float g_tmp1[BATCH * CDIM];

// ---------------------------------------------------------------------------
// Small GEMM: out[b,n] = bias[n] + sum_k X[b,k] * W[n,k], B=16 fixed.
// block = 256 (8 warps). Warp w -> column n0 + (w>>2), batches 4*(w&3)..+3.
// grid = N/2. Lanes stride K4 with float4 loads. Reduce = 5 shfls per batch.
// No shared memory, no block sync.
// ---------------------------------------------------------------------------
__global__ void __launch_bounds__(256) gemm16_w4(
    const float* __restrict__ X, const float* __restrict__ W,
    const float* __restrict__ bias, float* __restrict__ out, int K4, int N)
{
    const int warp = threadIdx.x >> 5;
    const int lane = threadIdx.x & 31;
    const int n    = blockIdx.x * 2 + (warp >> 2);
    const int b0   = (warp & 3) * 4;

    const float4* W4 = (const float4*)W + (size_t)n * K4;
    const float4* X4 = (const float4*)X + (size_t)b0 * K4;

    float a0 = 0.f, a1 = 0.f, a2 = 0.f, a3 = 0.f;

    for (int k4 = lane; k4 < K4; k4 += 32) {
        float4 w  = __ldg(W4 + k4);
        float4 x0 = __ldg(X4 + k4);
        float4 x1 = __ldg(X4 + K4 + k4);
        float4 x2 = __ldg(X4 + 2 * K4 + k4);
        float4 x3 = __ldg(X4 + 3 * K4 + k4);
        a0 += w.x * x0.x + w.y * x0.y + w.z * x0.z + w.w * x0.w;
        a1 += w.x * x1.x + w.y * x1.y + w.z * x1.z + w.w * x1.w;
        a2 += w.x * x2.x + w.y * x2.y + w.z * x2.z + w.w * x2.w;
        a3 += w.x * x3.x + w.y * x3.y + w.z * x3.z + w.w * x3.w;
    }
#pragma unroll
    for (int off = 16; off; off >>= 1) {
        a0 += __shfl_xor_sync(0xffffffffu, a0, off);
        a1 += __shfl_xor_sync(0xffffffffu, a1, off);
        a2 += __shfl_xor_sync(0xffffffffu, a2, off);
        a3 += __shfl_xor_sync(0xffffffffu, a3, off);
    }
    if (lane == 0) {
        float bs = __ldg(bias + n);
        out[(b0 + 0) * N + n] = a0 + bs;
        out[(b0 + 1) * N + n] = a1 + bs;
        out[(b0 + 2) * N + n] = a2 + bs;
        out[(b0 + 3) * N + n] = a3 + bs;
    }
}

// ---------------------------------------------------------------------------
// Fused broadcast-add + LayerNorm(C). Hybrid tile: 12 c-rows per thread in
// registers + 12 c-rows in SMEM (48 KB) -> regs <= 85, 3 blocks/SM.
// Thread map: p4 = tid&7 (float4 slot of 32-pixel row), c0 = tid>>3 (0..31).
// Spatial read exactly once from DRAM.
// ---------------------------------------------------------------------------
__global__ void __launch_bounds__(THREADS, 3) fused_add_ln(
    const float* __restrict__ spatial,
    const float* __restrict__ proj,
    const float* __restrict__ gamma,
    const float* __restrict__ beta,
    float* __restrict__ out)
{
    extern __shared__ float smem[];
    float* tile   = smem;                     // (24-REG_IT)*32 rows * PIX = 48 KB
    float* psum   = tile + (24 - REG_IT) * 32 * PIX;   // 8*PIX
    float* psq    = psum + 8 * PIX;                    // 8*PIX
    float* mean_s = psq  + 8 * PIX;                    // PIX
    float* rstd_s = mean_s + PIX;                      // PIX

    const int tid = threadIdx.x;
    const int b   = blockIdx.x >> 7;          // SDIM/PIX = 128 blocks/batch
    const int s0  = (blockIdx.x & 127) * PIX;

    const int p4   = tid & 7;                 // float4 slot within 32-pixel row
    const int c0   = tid >> 3;                // 0..31
    const int warp = tid >> 5;
    const int lane = tid & 31;

    const size_t gbase = (size_t)b * CDIM * SDIM + s0 + p4 * 4;
    const float* projb = proj + b * CDIM;

    float4 v[REG_IT];
    float acc[4] = {0.f, 0.f, 0.f, 0.f};
    float asq[4] = {0.f, 0.f, 0.f, 0.f};

    // ---- load + broadcast add + register stats (one DRAM read) ----
#pragma unroll
    for (int it = 0; it < 24; it++) {
        const int c = c0 + it * 32;
        float4 x = *(const float4*)(spatial + gbase + (size_t)c * SDIM);
        float pj = __ldg(projb + c);
        x.x += pj; x.y += pj; x.z += pj; x.w += pj;
        acc[0] += x.x; asq[0] += x.x * x.x;
        acc[1] += x.y; asq[1] += x.y * x.y;
        acc[2] += x.z; asq[2] += x.z * x.z;
        acc[3] += x.w; asq[3] += x.w * x.w;
        if (it < REG_IT) {
            v[it] = x;
        } else {
            // row r = (it-REG_IT)*32 + c0, slot p4
            *(float4*)(tile + ((it - REG_IT) * 32 + c0) * PIX + p4 * 4) = x;
        }
    }

    // ---- combine the 4 same-p4 lanes of this warp (lane bits 3,4) ----
#pragma unroll
    for (int q = 0; q < 4; q++) {
        acc[q] += __shfl_xor_sync(0xffffffffu, acc[q], 8);
        acc[q] += __shfl_xor_sync(0xffffffffu, acc[q], 16);
        asq[q] += __shfl_xor_sync(0xffffffffu, asq[q], 8);
        asq[q] += __shfl_xor_sync(0xffffffffu, asq[q], 16);
    }
    if (lane == p4) {                         // lanes 0..7
#pragma unroll
        for (int q = 0; q < 4; q++) {
            psum[warp * PIX + p4 * 4 + q] = acc[q];
            psq [warp * PIX + p4 * 4 + q] = asq[q];
        }
    }
    __syncthreads();

    // ---- final per-pixel stats ----
    if (tid < PIX) {
        float s = 0.f, sq = 0.f;
#pragma unroll
        for (int w = 0; w < 8; w++) { s += psum[w * PIX + tid]; sq += psq[w * PIX + tid]; }
        const float inv = 1.0f / CDIM;
        float mu  = s * inv;
        float var = sq * inv - mu * mu;
        mean_s[tid] = mu;
        rstd_s[tid] = rsqrtf(var + 1e-5f);
    }
    __syncthreads();

    // ---- normalize + store (register rows first, then smem rows) ----
    const float4 mu4 = *(const float4*)(mean_s + p4 * 4);
    const float4 rs4 = *(const float4*)(rstd_s + p4 * 4);
#pragma unroll
    for (int it = 0; it < REG_IT; it++) {
        const int c = c0 + it * 32;
        float g  = __ldg(gamma + c);
        float bt = __ldg(beta + c);
        float4 x = v[it];
        x.x = (x.x - mu4.x) * rs4.x * g + bt;
        x.y = (x.y - mu4.y) * rs4.y * g + bt;
        x.z = (x.z - mu4.z) * rs4.z * g + bt;
        x.w = (x.w - mu4.w) * rs4.w * g + bt;
        *(float4*)(out + gbase + (size_t)c * SDIM) = x;
    }
#pragma unroll
    for (int it = REG_IT; it < 24; it++) {
        const int c = c0 + it * 32;
        float g  = __ldg(gamma + c);
        float bt = __ldg(beta + c);
        float4 x = *(const float4*)(tile + ((it - REG_IT) * 32 + c0) * PIX + p4 * 4);
        x.x = (x.x - mu4.x) * rs4.x * g + bt;
        x.y = (x.y - mu4.y) * rs4.y * g + bt;
        x.z = (x.z - mu4.z) * rs4.z * g + bt;
        x.w = (x.w - mu4.w) * rs4.w * g + bt;
        *(float4*)(out + gbase + (size_t)c * SDIM) = x;
    }
}

// ---------------------------------------------------------------------------
// Launcher
// ---------------------------------------------------------------------------
extern "C" void kernel_launch(void* const* d_in, const int* in_sizes, int n_in,
                              void* d_out, int out_size)
{
    const float* spatial     = (const float*)d_in[0];
    const float* conditioning= (const float*)d_in[1];
    const float* w_cond      = (const float*)d_in[2];
    const float* b_cond      = (const float*)d_in[3];
    const float* in_proj_w   = (const float*)d_in[4];
    const float* in_proj_b   = (const float*)d_in[5];
    const float* attn_out_w  = (const float*)d_in[6];
    const float* attn_out_b  = (const float*)d_in[7];
    const float* w_out       = (const float*)d_in[8];
    const float* b_out       = (const float*)d_in[9];
    const float* ln_gamma    = (const float*)d_in[10];
    const float* ln_beta     = (const float*)d_in[11];
    float* out = (float*)d_out;

    float *tmp0, *tmp1;
    cudaGetSymbolAddress((void**)&tmp0, g_tmp0);
    cudaGetSymbolAddress((void**)&tmp1, g_tmp1);

    const int smem_bytes =
        ((24 - REG_IT) * 32 * PIX + 16 * PIX + 2 * PIX) * sizeof(float);
    cudaFuncSetAttribute(fused_add_ln, cudaFuncAttributeMaxDynamicSharedMemorySize,
                         smem_bytes);

    // 4-GEMM chain, grid = N/2 = 384 per launch
    gemm16_w4<<<CDIM / 2, 256>>>(conditioning, w_cond, b_cond, tmp0, KCOND / 4, CDIM);
    gemm16_w4<<<CDIM / 2, 256>>>(tmp0, in_proj_w + 2 * CDIM * CDIM,
                                 in_proj_b + 2 * CDIM, tmp1, CDIM / 4, CDIM);
    gemm16_w4<<<CDIM / 2, 256>>>(tmp1, attn_out_w, attn_out_b, tmp0, CDIM / 4, CDIM);
    gemm16_w4<<<CDIM / 2, 256>>>(tmp0, w_out, b_out, tmp1, CDIM / 4, CDIM);

    // fused add + layernorm (proj lives in g_tmp1)
    fused_add_ln<<<BATCH * (SDIM / PIX), THREADS, smem_bytes>>>(
        spatial, tmp1, ln_gamma, ln_beta, out);
}

// round 6
// speedup vs baseline: 1.5115x; 1.0429x over previous
#include <cuda_runtime.h>
#include <cstdint>

// ---------------------------------------------------------------------------
// Problem constants
// ---------------------------------------------------------------------------
#define BATCH 16
#define CDIM  768
#define SDIM  4096          // H*W = 64*64
#define KCOND 1024

#define PIX     32          // pixels per LN block
#define THREADS 256
#define REG_IT  12          // c-iterations kept in registers (of 24)

// ---------------------------------------------------------------------------
// Scratch (no allocations allowed -> device globals)
// ---------------------------------------------------------------------------
__device__ __align__(16) float g_tmp0[BATCH * CDIM];
__device__ __align__(16) float g_tmp1[BATCH * CDIM];

// ---------------------------------------------------------------------------
// Small GEMM: out[b,n] = bias[n] + sum_k X[b,k] * W[n,k], B=16 fixed.
// K4 compile-time -> fully unrolled k-loop -> all loads issued up front.
// block = 512 (16 warps): warp w -> column n0+(w>>3), batches 2*(w&7)..+1.
// grid = N/2 = 384. No smem, no block sync; 10-shfl reduce tail per warp.
// ---------------------------------------------------------------------------
template<int K4>
__global__ void __launch_bounds__(512) gemm16_tpl(
    const float* __restrict__ X, const float* __restrict__ W,
    const float* __restrict__ bias, float* __restrict__ out, int N)
{
    const int warp = threadIdx.x >> 5;       // 0..15
    const int lane = threadIdx.x & 31;
    const int n    = blockIdx.x * 2 + (warp >> 3);
    const int b0   = (warp & 7) * 2;

    const float4* W4 = (const float4*)W + (size_t)n * K4;
    const float4* X4 = (const float4*)X + (size_t)b0 * K4;

    float a0 = 0.f, a1 = 0.f;
#pragma unroll
    for (int i = 0; i < K4 / 32; i++) {
        const int k4 = lane + i * 32;
        float4 w  = __ldg(W4 + k4);
        float4 x0 = __ldg(X4 + k4);
        float4 x1 = __ldg(X4 + K4 + k4);
        a0 += w.x * x0.x + w.y * x0.y + w.z * x0.z + w.w * x0.w;
        a1 += w.x * x1.x + w.y * x1.y + w.z * x1.z + w.w * x1.w;
    }
#pragma unroll
    for (int off = 16; off; off >>= 1) {
        a0 += __shfl_xor_sync(0xffffffffu, a0, off);
        a1 += __shfl_xor_sync(0xffffffffu, a1, off);
    }
    if (lane == 0) {
        float bs = __ldg(bias + n);
        out[(b0 + 0) * N + n] = a0 + bs;
        out[(b0 + 1) * N + n] = a1 + bs;
    }
}

// ---------------------------------------------------------------------------
// Fused broadcast-add + LayerNorm(C). Hybrid tile: 12 c-rows per thread in
// registers + 12 c-rows in SMEM (48 KB) -> 3 blocks/SM.
// Thread map: p4 = tid&7 (float4 slot of 32-pixel row), c0 = tid>>3 (0..31).
// Spatial read exactly once from DRAM.
// ---------------------------------------------------------------------------
__global__ void __launch_bounds__(THREADS, 3) fused_add_ln(
    const float* __restrict__ spatial,
    const float* __restrict__ proj,
    const float* __restrict__ gamma,
    const float* __restrict__ beta,
    float* __restrict__ out)
{
    extern __shared__ float smem[];
    float* tile   = smem;                              // (24-REG_IT)*32*PIX
    float* psum   = tile + (24 - REG_IT) * 32 * PIX;   // 8*PIX
    float* psq    = psum + 8 * PIX;                    // 8*PIX
    float* mean_s = psq  + 8 * PIX;                    // PIX
    float* rstd_s = mean_s + PIX;                      // PIX

    const int tid = threadIdx.x;
    const int b   = blockIdx.x >> 7;          // SDIM/PIX = 128 blocks/batch
    const int s0  = (blockIdx.x & 127) * PIX;

    const int p4   = tid & 7;                 // float4 slot within 32-pixel row
    const int c0   = tid >> 3;                // 0..31
    const int warp = tid >> 5;
    const int lane = tid & 31;

    const size_t gbase = (size_t)b * CDIM * SDIM + s0 + p4 * 4;
    const float* projb = proj + b * CDIM;

    float4 v[REG_IT];
    float acc[4] = {0.f, 0.f, 0.f, 0.f};
    float asq[4] = {0.f, 0.f, 0.f, 0.f};

    // ---- load + broadcast add + register stats (one DRAM read) ----
#pragma unroll
    for (int it = 0; it < 24; it++) {
        const int c = c0 + it * 32;
        float4 x = *(const float4*)(spatial + gbase + (size_t)c * SDIM);
        float pj = __ldg(projb + c);
        x.x += pj; x.y += pj; x.z += pj; x.w += pj;
        acc[0] += x.x; asq[0] += x.x * x.x;
        acc[1] += x.y; asq[1] += x.y * x.y;
        acc[2] += x.z; asq[2] += x.z * x.z;
        acc[3] += x.w; asq[3] += x.w * x.w;
        if (it < REG_IT) {
            v[it] = x;
        } else {
            *(float4*)(tile + ((it - REG_IT) * 32 + c0) * PIX + p4 * 4) = x;
        }
    }

    // ---- combine the 4 same-p4 lanes of this warp (lane bits 3,4) ----
#pragma unroll
    for (int q = 0; q < 4; q++) {
        acc[q] += __shfl_xor_sync(0xffffffffu, acc[q], 8);
        acc[q] += __shfl_xor_sync(0xffffffffu, acc[q], 16);
        asq[q] += __shfl_xor_sync(0xffffffffu, asq[q], 8);
        asq[q] += __shfl_xor_sync(0xffffffffu, asq[q], 16);
    }
    if (lane == p4) {                         // lanes 0..7
#pragma unroll
        for (int q = 0; q < 4; q++) {
            psum[warp * PIX + p4 * 4 + q] = acc[q];
            psq [warp * PIX + p4 * 4 + q] = asq[q];
        }
    }
    __syncthreads();

    // ---- final per-pixel stats ----
    if (tid < PIX) {
        float s = 0.f, sq = 0.f;
#pragma unroll
        for (int w = 0; w < 8; w++) { s += psum[w * PIX + tid]; sq += psq[w * PIX + tid]; }
        const float inv = 1.0f / CDIM;
        float mu  = s * inv;
        float var = sq * inv - mu * mu;
        mean_s[tid] = mu;
        rstd_s[tid] = rsqrtf(var + 1e-5f);
    }
    __syncthreads();

    // ---- normalize + store (register rows first, then smem rows) ----
    const float4 mu4 = *(const float4*)(mean_s + p4 * 4);
    const float4 rs4 = *(const float4*)(rstd_s + p4 * 4);
#pragma unroll
    for (int it = 0; it < REG_IT; it++) {
        const int c = c0 + it * 32;
        float g  = __ldg(gamma + c);
        float bt = __ldg(beta + c);
        float4 x = v[it];
        x.x = (x.x - mu4.x) * rs4.x * g + bt;
        x.y = (x.y - mu4.y) * rs4.y * g + bt;
        x.z = (x.z - mu4.z) * rs4.z * g + bt;
        x.w = (x.w - mu4.w) * rs4.w * g + bt;
        *(float4*)(out + gbase + (size_t)c * SDIM) = x;
    }
#pragma unroll
    for (int it = REG_IT; it < 24; it++) {
        const int c = c0 + it * 32;
        float g  = __ldg(gamma + c);
        float bt = __ldg(beta + c);
        float4 x = *(const float4*)(tile + ((it - REG_IT) * 32 + c0) * PIX + p4 * 4);
        x.x = (x.x - mu4.x) * rs4.x * g + bt;
        x.y = (x.y - mu4.y) * rs4.y * g + bt;
        x.z = (x.z - mu4.z) * rs4.z * g + bt;
        x.w = (x.w - mu4.w) * rs4.w * g + bt;
        *(float4*)(out + gbase + (size_t)c * SDIM) = x;
    }
}

// ---------------------------------------------------------------------------
// Launcher
// ---------------------------------------------------------------------------
extern "C" void kernel_launch(void* const* d_in, const int* in_sizes, int n_in,
                              void* d_out, int out_size)
{
    const float* spatial     = (const float*)d_in[0];
    const float* conditioning= (const float*)d_in[1];
    const float* w_cond      = (const float*)d_in[2];
    const float* b_cond      = (const float*)d_in[3];
    const float* in_proj_w   = (const float*)d_in[4];
    const float* in_proj_b   = (const float*)d_in[5];
    const float* attn_out_w  = (const float*)d_in[6];
    const float* attn_out_b  = (const float*)d_in[7];
    const float* w_out       = (const float*)d_in[8];
    const float* b_out       = (const float*)d_in[9];
    const float* ln_gamma    = (const float*)d_in[10];
    const float* ln_beta     = (const float*)d_in[11];
    float* out = (float*)d_out;

    float *tmp0, *tmp1;
    cudaGetSymbolAddress((void**)&tmp0, g_tmp0);
    cudaGetSymbolAddress((void**)&tmp1, g_tmp1);

    const int smem_bytes =
        ((24 - REG_IT) * 32 * PIX + 16 * PIX + 2 * PIX) * sizeof(float);
    cudaFuncSetAttribute(fused_add_ln, cudaFuncAttributeMaxDynamicSharedMemorySize,
                         smem_bytes);

    // 4-GEMM chain: templated K for full unroll, grid = N/2 = 384, block 512
    gemm16_tpl<KCOND / 4><<<CDIM / 2, 512>>>(conditioning, w_cond, b_cond, tmp0, CDIM);
    gemm16_tpl<CDIM  / 4><<<CDIM / 2, 512>>>(tmp0, in_proj_w + 2 * CDIM * CDIM,
                                             in_proj_b + 2 * CDIM, tmp1, CDIM);
    gemm16_tpl<CDIM  / 4><<<CDIM / 2, 512>>>(tmp1, attn_out_w, attn_out_b, tmp0, CDIM);
    gemm16_tpl<CDIM  / 4><<<CDIM / 2, 512>>>(tmp0, w_out, b_out, tmp1, CDIM);

    // fused add + layernorm (proj lives in g_tmp1)
    fused_add_ln<<<BATCH * (SDIM / PIX), THREADS, smem_bytes>>>(
        spatial, tmp1, ln_gamma, ln_beta, out);
}